// round 16
// baseline (speedup 1.0000x reference)
#include <cuda_runtime.h>
#include <cstdint>

#define WW 256
#define D4 64            // 256 channels as float4
#define NB 2048
#define RS 528           // smem row stride in words: 528 % 32 == 16
#define TI 16            // tiles: 16 rows x 32 cols -> 16 x 8 = 128 tiles

// Compact buffers only — the full 64MB SAT is never materialized.
__device__ float4 g_corner[NB * 4 * D4];       // [box*4+ct][d4]  (8 MB)
__device__ float4 g_bot[128 * 32 * D4];        // [tile][c][d4]   tileSAT(15,c)
__device__ float4 g_right[128 * 16 * D4];      // [tile][r][d4]   tileSAT(r,31)
__device__ float4 g_rowcum[16 * 8 * 16 * D4];  // [ti][tj][r][d4]
__device__ float4 g_colcum[16 * 8 * 32 * D4];  // [ti][tj][c][d4]
__device__ float4 g_blockcum[16 * 8 * D4];     // [ti][tj][d4]
__device__ int      g_tilestart[128];
__device__ int      g_tilecnt[128];
__device__ uint32_t g_tilelist[NB * 4];        // packed (key<<9 | rloc<<5 | cloc)

__device__ __forceinline__ void acc4(float4& a, const float4 v) {
    a.x += v.x; a.y += v.y; a.z += v.z; a.w += v.w;
}

__device__ __forceinline__ uint32_t smem_u32(const void* p) {
    return (uint32_t)__cvta_generic_to_shared(p);
}

// _bounds per reference: lo = max(0, floor(lo_f*256)); hi = rint(hi_f*256+0.5);
// hi = min(256, max(lo+1, hi)). No FMA contraction (match jax).
__device__ __forceinline__ void bounds4(const float* __restrict__ boxes, int n,
                                        int& clo, int& chi, int& rlo, int& rhi) {
    float x1 = boxes[n * 4 + 0], y1 = boxes[n * 4 + 1];
    float x2 = boxes[n * 4 + 2], y2 = boxes[n * 4 + 3];
    clo = max(0, (int)floorf(__fmul_rn(x1, 256.0f)));
    chi = (int)rintf(__fadd_rn(__fmul_rn(x2, 256.0f), 0.5f));
    chi = min(WW, max(clo + 1, chi));
    rlo = max(0, (int)floorf(__fmul_rn(y1, 256.0f)));
    rhi = (int)rintf(__fadd_rn(__fmul_rn(y2, 256.0f), 0.5f));
    rhi = min(256, max(rlo + 1, rhi));
}

// ---------------------------------------------------------------------------
// Binning: single block, smem counters (stateless across replays). Builds
// per-tile lists of the 4 corner pixels of every box.
// ---------------------------------------------------------------------------
__global__ void __launch_bounds__(256) binning(const float* __restrict__ boxes) {
    __shared__ int cnt[128], off[128];
    int t = threadIdx.x;
    if (t < 128) cnt[t] = 0;
    __syncthreads();

    for (int n = t; n < NB; n += 256) {
        int clo, chi, rlo, rhi;
        bounds4(boxes, n, clo, chi, rlo, rhi);
        int rr[4] = { rhi - 1, max(rlo - 1, 0), rhi - 1, max(rlo - 1, 0) };
        int cc[4] = { chi - 1, chi - 1, max(clo - 1, 0), max(clo - 1, 0) };
#pragma unroll
        for (int ct = 0; ct < 4; ++ct)
            atomicAdd(&cnt[(rr[ct] >> 4) * 8 + (cc[ct] >> 5)], 1);
    }
    __syncthreads();
    if (t == 0) {
        int s = 0;
        for (int i = 0; i < 128; ++i) { off[i] = s; s += cnt[i]; }
    }
    __syncthreads();
    if (t < 128) { g_tilestart[t] = off[t]; g_tilecnt[t] = cnt[t]; cnt[t] = 0; }
    __syncthreads();

    for (int n = t; n < NB; n += 256) {
        int clo, chi, rlo, rhi;
        bounds4(boxes, n, clo, chi, rlo, rhi);
        int rr[4] = { rhi - 1, max(rlo - 1, 0), rhi - 1, max(rlo - 1, 0) };
        int cc[4] = { chi - 1, chi - 1, max(clo - 1, 0), max(clo - 1, 0) };
#pragma unroll
        for (int ct = 0; ct < 4; ++ct) {
            int tile = (rr[ct] >> 4) * 8 + (cc[ct] >> 5);
            int slot = atomicAdd(&cnt[tile], 1);
            uint32_t key = (uint32_t)(n * 4 + ct);
            g_tilelist[off[tile] + slot] =
                (key << 9) | ((uint32_t)(rr[ct] & 15) << 5) | (uint32_t)(cc[ct] & 31);
        }
    }
}

// ---------------------------------------------------------------------------
// Tile SAT: 16x32 pixels x 16 channels per block, 2048 blocks x 128 threads.
// Same scan structure as the 37.3us best, but the tile SAT stays in SMEM:
// only compact edges + the listed corner values are written to gmem.
// ---------------------------------------------------------------------------
__global__ void __launch_bounds__(128, 6) sat_tile(const float4* __restrict__ feat) {
    extern __shared__ float sm[];                 // 16*RS + 256 words = 34816 B
    float* carry = &sm[16 * RS];
    int b     = blockIdx.x;
    int dgrp  = b & 15;
    int tj    = (b >> 4) & 7;
    int ti    = b >> 7;
    int tile  = ti * 8 + tj;
    int t     = threadIdx.x;
    int kw4   = t & 3;
    int h0 = ti * TI, w0 = tj * 32;
    int c0 = dgrp * 4;

    uint64_t pol;
    asm volatile("createpolicy.fractional.L2::evict_first.b64 %0, 1.0;" : "=l"(pol));

    // ---- Phase A: row scan of 16 columns per thread (cols split by chalf).
    {
        int u     = (t >> 2) & 15;
        int chalf = t >> 6;
        int cb    = chalf * 16;
        const float4* __restrict__ src =
            feat + ((size_t)(h0 + u) * WW + w0 + cb) * D4 + c0 + kw4;
        uint32_t sdst = smem_u32(&sm[u * RS + cb * 16 + kw4 * 4]);

#pragma unroll
        for (int g = 0; g < 2; ++g) {
#pragma unroll
            for (int j = 0; j < 8; ++j) {
                int c = g * 8 + j;
                asm volatile(
                    "cp.async.cg.shared.global.L2::cache_hint [%0], [%1], 16, %2;\n"
                    :: "r"(sdst + c * 64), "l"(src + (size_t)c * D4), "l"(pol)
                    : "memory");
            }
            asm volatile("cp.async.commit_group;\n" ::: "memory");
        }

        float* __restrict__ srow = &sm[u * RS + cb * 16 + kw4 * 4];
        float4 acc = make_float4(0.f, 0.f, 0.f, 0.f);
        float4 buf[8];
#pragma unroll
        for (int g = 0; g < 2; ++g) {
            if (g == 0) asm volatile("cp.async.wait_group 1;\n" ::: "memory");
            else        asm volatile("cp.async.wait_group 0;\n" ::: "memory");
#pragma unroll
            for (int j = 0; j < 8; ++j)
                buf[j] = *reinterpret_cast<const float4*>(&srow[(g * 8 + j) * 16]);
#pragma unroll
            for (int j = 0; j < 8; ++j) {
                acc4(acc, buf[j]);
                *reinterpret_cast<float4*>(&srow[(g * 8 + j) * 16]) = acc;
            }
        }
        if (chalf == 0)
            *reinterpret_cast<float4*>(&carry[(u * 4 + kw4) * 4]) = acc;
    }
    __syncthreads();

    // ---- Phase B: col scan IN SMEM (complete row prefix + column prefix).
    {
        int c = t >> 2;
        bool needc = (c >= 16);
        float* __restrict__ scol = &sm[c * 16 + kw4 * 4];
        const float* __restrict__ carr = &carry[kw4 * 4];
        float4 acc = make_float4(0.f, 0.f, 0.f, 0.f);
        float4 buf[8], cbuf[8];
#pragma unroll
        for (int rr = 0; rr < 16; rr += 8) {
#pragma unroll
            for (int j = 0; j < 8; ++j) {
                buf[j]  = *reinterpret_cast<const float4*>(&scol[(rr + j) * RS]);
                cbuf[j] = *reinterpret_cast<const float4*>(&carr[(rr + j) * 16]);
            }
#pragma unroll
            for (int j = 0; j < 8; ++j) {
                float4 v = buf[j];
                if (needc) acc4(v, cbuf[j]);
                acc4(acc, v);
                *reinterpret_cast<float4*>(&scol[(rr + j) * RS]) = acc;
            }
        }
        // bottom edge: acc == tileSAT(15, c)
        g_bot[((size_t)tile * 32 + c) * D4 + c0 + kw4] = acc;
    }
    __syncthreads();

    // ---- Right edge: tileSAT(r, 31), r = 0..15 (64 threads).
    if (t < 64) {
        int r = t >> 2;
        float4 v = *reinterpret_cast<const float4*>(&sm[r * RS + 31 * 16 + kw4 * 4]);
        g_right[((size_t)tile * 16 + r) * D4 + c0 + kw4] = v;
    }

    // ---- Corner emission: 32 corners per iteration (4 lanes each).
    {
        int n = g_tilecnt[tile];
        int start = g_tilestart[tile];
        for (int i0 = 0; i0 < n; i0 += 32) {
            int idx = i0 + (t >> 2);
            if (idx < n) {
                uint32_t e = g_tilelist[start + idx];
                int cloc = e & 31, rloc = (e >> 5) & 15;
                uint32_t key = e >> 9;                 // box*4 + ct
                float4 v = *reinterpret_cast<const float4*>(
                    &sm[rloc * RS + cloc * 16 + kw4 * 4]);
                g_corner[(size_t)key * D4 + c0 + kw4] = v;
            }
        }
    }
}

// ---------------------------------------------------------------------------
// Fixups (R11's exact measured-best form, reading compact edge buffers):
//   [0, 16384)      rowcum:   thread (ti, r, d4), 7 edge loads, scan tj
//   [16384, 32768)  colcum:   thread (tj, c, d4), 15 edge loads, scan ti
//   [32768, 33280)  blockcum: thread (tj, d4), serial scan over ti
// ---------------------------------------------------------------------------
__global__ void __launch_bounds__(256) fixups() {
    int flat = blockIdx.x * 256 + threadIdx.x;
    if (flat < 16384) {                        // rowcum
        int d4 = flat & 63, r = (flat >> 6) & 15, ti = flat >> 10;
        float4 e[7];
#pragma unroll
        for (int s = 0; s < 7; ++s)
            e[s] = g_right[((size_t)(ti * 8 + s) * 16 + r) * D4 + d4];
        float4 acc = make_float4(0.f, 0.f, 0.f, 0.f);
#pragma unroll
        for (int tj = 0; tj < 8; ++tj) {
            g_rowcum[((ti * 8 + tj) * 16 + r) * 64 + d4] = acc;
            if (tj < 7) acc4(acc, e[tj]);
        }
    } else if (flat < 32768) {                 // colcum
        int f = flat - 16384;
        int d4 = f & 63, c = (f >> 6) & 31, tj = f >> 11;
        float4 e[15];
#pragma unroll
        for (int s = 0; s < 15; ++s)
            e[s] = g_bot[((size_t)(s * 8 + tj) * 32 + c) * D4 + d4];
        float4 acc = make_float4(0.f, 0.f, 0.f, 0.f);
#pragma unroll
        for (int ti = 0; ti < 16; ++ti) {
            g_colcum[((ti * 8 + tj) * 32 + c) * 64 + d4] = acc;
            if (ti < 15) acc4(acc, e[ti]);
        }
    } else if (flat < 33280) {                 // blockcum
        int f = flat - 32768;
        int d4 = f & 63, tj = f >> 6;
        float4 acc = make_float4(0.f, 0.f, 0.f, 0.f);
#pragma unroll
        for (int ti = 0; ti < 16; ++ti) {
            g_blockcum[(ti * 8 + tj) * 64 + d4] = acc;
            float4 e[7];
#pragma unroll
            for (int s = 0; s < 7; ++s)
                e[s] = g_bot[((size_t)(ti * 8 + s) * 32 + 31) * D4 + d4];
#pragma unroll
            for (int s = 0; s < 7; ++s)
                if (s < tj) acc4(acc, e[s]);
        }
    }
}

// Corner SAT value: stored tile partial + the three cum tables.
__device__ __forceinline__ float4 cornerval(int n, int ct, int r, int c, int d4) {
    int ti = r >> 4, tj = c >> 5;
    float4 v = g_corner[(size_t)(n * 4 + ct) * D4 + d4];
    acc4(v, g_rowcum[((ti * 8 + tj) * 16 + (r & 15)) * 64 + d4]);
    acc4(v, g_colcum[((ti * 8 + tj) * 32 + (c & 31)) * 64 + d4]);
    acc4(v, g_blockcum[(ti * 8 + tj) * 64 + d4]);
    return v;
}

// ---------------------------------------------------------------------------
// Gather: 4 boxes per block, 64 float4 lanes per box. Corner base loads are
// now fully coalesced (keyed by box*4+ct); tables are small and L2/L1-hit.
// ---------------------------------------------------------------------------
__global__ void __launch_bounds__(256) roi_gather(const float* __restrict__ boxes,
                                                  float4* __restrict__ out) {
    int n  = blockIdx.x * 4 + (threadIdx.x >> 6);
    int d4 = threadIdx.x & 63;

    int clo, chi, rlo, rhi;
    bounds4(boxes, n, clo, chi, rlo, rhi);
    int r2 = rhi - 1, c2 = chi - 1;
    int r1 = max(rlo - 1, 0), c1 = max(clo - 1, 0);

    float4 s = cornerval(n, 0, r2, c2, d4);
    if (rlo > 0) {
        float4 a = cornerval(n, 1, r1, c2, d4);
        s.x -= a.x; s.y -= a.y; s.z -= a.z; s.w -= a.w;
    }
    if (clo > 0) {
        float4 bb = cornerval(n, 2, r2, c1, d4);
        s.x -= bb.x; s.y -= bb.y; s.z -= bb.z; s.w -= bb.w;
        if (rlo > 0) acc4(s, cornerval(n, 3, r1, c1, d4));
    }

    float inv = 1.0f / (float)((rhi - rlo) * (chi - clo));
    s.x *= inv; s.y *= inv; s.z *= inv; s.w *= inv;
    out[(size_t)n * D4 + d4] = s;
}

extern "C" void kernel_launch(void* const* d_in, const int* in_sizes, int n_in,
                              void* d_out, int out_size) {
    const float4* feat  = (const float4*)d_in[0];   // (256,256,256) fp32
    const float*  boxes = (const float*)d_in[1];    // (2048,4) fp32
    float4* out = (float4*)d_out;                   // (2048,256) fp32

    const int smem = (16 * RS + 16 * 4 * 4) * 4;    // 34816 B -> 6 blocks/SM
    cudaFuncSetAttribute(sat_tile, cudaFuncAttributeMaxDynamicSharedMemorySize, smem);

    binning<<<1, 256>>>(boxes);
    sat_tile<<<2048, 128, smem>>>(feat);
    fixups<<<130, 256>>>();                         // 33280 threads
    roi_gather<<<NB / 4, 256>>>(boxes, out);
}

// round 17
// speedup vs baseline: 1.1233x; 1.1233x over previous
#include <cuda_runtime.h>
#include <cstdint>

#define WW 256
#define D4 64            // 256 channels as float4
#define NB 2048
#define RS 528           // smem row stride in words: 528 % 32 == 16
#define TI 16            // tiles: 16 rows x 32 cols -> 16 x 8 = 128 tiles
#define CAP 8192         // per-tile corner-list capacity (worst case)

// Compact buffers only — the full 64MB SAT is never materialized, so the
// working set (feat 64MB + ~20MB here) stays L2-resident across replays.
__device__ float4 g_corner[NB * 4 * D4];       // [box*4+ct][d4]  (8 MB)
__device__ float4 g_bot[128 * 32 * D4];        // [tile][c][d4]   tileSAT(15,c)
__device__ float4 g_right[128 * 16 * D4];      // [tile][r][d4]   tileSAT(r,31)
__device__ float4 g_rowcum[16 * 8 * 16 * D4];  // [ti][tj][r][d4]
__device__ float4 g_colcum[16 * 8 * 32 * D4];  // [ti][tj][c][d4]
__device__ float4 g_blockcum[16 * 8 * D4];     // [ti][tj][d4]
__device__ int      g_tilecnt[128];            // zero-init; reset by roi_gather
__device__ uint32_t g_tilelist[128 * CAP];     // packed (key<<9 | rloc<<5 | cloc)

__device__ __forceinline__ void acc4(float4& a, const float4 v) {
    a.x += v.x; a.y += v.y; a.z += v.z; a.w += v.w;
}

__device__ __forceinline__ uint32_t smem_u32(const void* p) {
    return (uint32_t)__cvta_generic_to_shared(p);
}

// _bounds per reference: lo = max(0, floor(lo_f*256)); hi = rint(hi_f*256+0.5);
// hi = min(256, max(lo+1, hi)). No FMA contraction (match jax).
__device__ __forceinline__ void bounds4(const float* __restrict__ boxes, int n,
                                        int& clo, int& chi, int& rlo, int& rhi) {
    float x1 = boxes[n * 4 + 0], y1 = boxes[n * 4 + 1];
    float x2 = boxes[n * 4 + 2], y2 = boxes[n * 4 + 3];
    clo = max(0, (int)floorf(__fmul_rn(x1, 256.0f)));
    chi = (int)rintf(__fadd_rn(__fmul_rn(x2, 256.0f), 0.5f));
    chi = min(WW, max(clo + 1, chi));
    rlo = max(0, (int)floorf(__fmul_rn(y1, 256.0f)));
    rhi = (int)rintf(__fadd_rn(__fmul_rn(y2, 256.0f), 0.5f));
    rhi = min(256, max(rlo + 1, rhi));
}

// ---------------------------------------------------------------------------
// Binning: 8 blocks x 256 threads, one box per thread, single pass.
// Fixed-capacity per-tile slots via global atomics -> no prefix scan, no
// second pass. Slot ORDER is nondeterministic but g_corner[key] values are
// order-independent, so the output is deterministic. g_tilecnt starts at 0
// (static init on first run, reset by roi_gather afterwards).
// ---------------------------------------------------------------------------
__global__ void __launch_bounds__(256) binning(const float* __restrict__ boxes) {
    int n = blockIdx.x * 256 + threadIdx.x;
    int clo, chi, rlo, rhi;
    bounds4(boxes, n, clo, chi, rlo, rhi);
    int rr[4] = { rhi - 1, max(rlo - 1, 0), rhi - 1, max(rlo - 1, 0) };
    int cc[4] = { chi - 1, chi - 1, max(clo - 1, 0), max(clo - 1, 0) };
#pragma unroll
    for (int ct = 0; ct < 4; ++ct) {
        int tile = (rr[ct] >> 4) * 8 + (cc[ct] >> 5);
        int slot = atomicAdd(&g_tilecnt[tile], 1);
        uint32_t key = (uint32_t)(n * 4 + ct);
        g_tilelist[tile * CAP + slot] =
            (key << 9) | ((uint32_t)(rr[ct] & 15) << 5) | (uint32_t)(cc[ct] & 31);
    }
}

// ---------------------------------------------------------------------------
// Tile SAT: 16x32 pixels x 16 channels per block, 2048 blocks x 128 threads.
// Scan structure identical to the measured-best; tile SAT stays in SMEM and
// only compact edges + listed corner values are written out.
// ---------------------------------------------------------------------------
__global__ void __launch_bounds__(128, 6) sat_tile(const float4* __restrict__ feat) {
    extern __shared__ float sm[];                 // 16*RS + 256 words = 34816 B
    float* carry = &sm[16 * RS];
    int b     = blockIdx.x;
    int dgrp  = b & 15;
    int tj    = (b >> 4) & 7;
    int ti    = b >> 7;
    int tile  = ti * 8 + tj;
    int t     = threadIdx.x;
    int kw4   = t & 3;
    int h0 = ti * TI, w0 = tj * 32;
    int c0 = dgrp * 4;

    // ---- Phase A: row scan of 16 columns per thread (cols split by chalf).
    {
        int u     = (t >> 2) & 15;
        int chalf = t >> 6;
        int cb    = chalf * 16;
        const float4* __restrict__ src =
            feat + ((size_t)(h0 + u) * WW + w0 + cb) * D4 + c0 + kw4;
        uint32_t sdst = smem_u32(&sm[u * RS + cb * 16 + kw4 * 4]);

#pragma unroll
        for (int g = 0; g < 2; ++g) {
#pragma unroll
            for (int j = 0; j < 8; ++j) {
                int c = g * 8 + j;
                asm volatile("cp.async.cg.shared.global [%0], [%1], 16;\n"
                             :: "r"(sdst + c * 64), "l"(src + (size_t)c * D4)
                             : "memory");
            }
            asm volatile("cp.async.commit_group;\n" ::: "memory");
        }

        float* __restrict__ srow = &sm[u * RS + cb * 16 + kw4 * 4];
        float4 acc = make_float4(0.f, 0.f, 0.f, 0.f);
        float4 buf[8];
#pragma unroll
        for (int g = 0; g < 2; ++g) {
            if (g == 0) asm volatile("cp.async.wait_group 1;\n" ::: "memory");
            else        asm volatile("cp.async.wait_group 0;\n" ::: "memory");
#pragma unroll
            for (int j = 0; j < 8; ++j)
                buf[j] = *reinterpret_cast<const float4*>(&srow[(g * 8 + j) * 16]);
#pragma unroll
            for (int j = 0; j < 8; ++j) {
                acc4(acc, buf[j]);
                *reinterpret_cast<float4*>(&srow[(g * 8 + j) * 16]) = acc;
            }
        }
        if (chalf == 0)
            *reinterpret_cast<float4*>(&carry[(u * 4 + kw4) * 4]) = acc;
    }
    __syncthreads();

    // ---- Phase B: col scan IN SMEM (complete row prefix + column prefix).
    {
        int c = t >> 2;
        bool needc = (c >= 16);
        float* __restrict__ scol = &sm[c * 16 + kw4 * 4];
        const float* __restrict__ carr = &carry[kw4 * 4];
        float4 acc = make_float4(0.f, 0.f, 0.f, 0.f);
        float4 buf[8], cbuf[8];
#pragma unroll
        for (int rr = 0; rr < 16; rr += 8) {
#pragma unroll
            for (int j = 0; j < 8; ++j) {
                buf[j]  = *reinterpret_cast<const float4*>(&scol[(rr + j) * RS]);
                cbuf[j] = *reinterpret_cast<const float4*>(&carr[(rr + j) * 16]);
            }
#pragma unroll
            for (int j = 0; j < 8; ++j) {
                float4 v = buf[j];
                if (needc) acc4(v, cbuf[j]);
                acc4(acc, v);
                *reinterpret_cast<float4*>(&scol[(rr + j) * RS]) = acc;
            }
        }
        g_bot[((size_t)tile * 32 + c) * D4 + c0 + kw4] = acc;  // tileSAT(15,c)
    }
    __syncthreads();

    // ---- Right edge: tileSAT(r, 31), r = 0..15 (64 threads).
    if (t < 64) {
        int r = t >> 2;
        float4 v = *reinterpret_cast<const float4*>(&sm[r * RS + 31 * 16 + kw4 * 4]);
        g_right[((size_t)tile * 16 + r) * D4 + c0 + kw4] = v;
    }

    // ---- Corner emission: 32 corners per iteration (4 lanes each).
    {
        int n = g_tilecnt[tile];
        const uint32_t* __restrict__ list = &g_tilelist[tile * CAP];
        for (int i0 = 0; i0 < n; i0 += 32) {
            int idx = i0 + (t >> 2);
            if (idx < n) {
                uint32_t e = list[idx];
                int cloc = e & 31, rloc = (e >> 5) & 15;
                uint32_t key = e >> 9;                 // box*4 + ct
                float4 v = *reinterpret_cast<const float4*>(
                    &sm[rloc * RS + cloc * 16 + kw4 * 4]);
                g_corner[(size_t)key * D4 + c0 + kw4] = v;
            }
        }
    }
}

// ---------------------------------------------------------------------------
// Fixups (measured-best form, reading compact edge buffers):
//   [0, 16384)      rowcum:   thread (ti, r, d4), 7 edge loads, scan tj
//   [16384, 32768)  colcum:   thread (tj, c, d4), 15 edge loads, scan ti
//   [32768, 33280)  blockcum: thread (tj, d4), serial scan over ti
// ---------------------------------------------------------------------------
__global__ void __launch_bounds__(256) fixups() {
    int flat = blockIdx.x * 256 + threadIdx.x;
    if (flat < 16384) {                        // rowcum
        int d4 = flat & 63, r = (flat >> 6) & 15, ti = flat >> 10;
        float4 e[7];
#pragma unroll
        for (int s = 0; s < 7; ++s)
            e[s] = g_right[((size_t)(ti * 8 + s) * 16 + r) * D4 + d4];
        float4 acc = make_float4(0.f, 0.f, 0.f, 0.f);
#pragma unroll
        for (int tj = 0; tj < 8; ++tj) {
            g_rowcum[((ti * 8 + tj) * 16 + r) * 64 + d4] = acc;
            if (tj < 7) acc4(acc, e[tj]);
        }
    } else if (flat < 32768) {                 // colcum
        int f = flat - 16384;
        int d4 = f & 63, c = (f >> 6) & 31, tj = f >> 11;
        float4 e[15];
#pragma unroll
        for (int s = 0; s < 15; ++s)
            e[s] = g_bot[((size_t)(s * 8 + tj) * 32 + c) * D4 + d4];
        float4 acc = make_float4(0.f, 0.f, 0.f, 0.f);
#pragma unroll
        for (int ti = 0; ti < 16; ++ti) {
            g_colcum[((ti * 8 + tj) * 32 + c) * 64 + d4] = acc;
            if (ti < 15) acc4(acc, e[ti]);
        }
    } else if (flat < 33280) {                 // blockcum
        int f = flat - 32768;
        int d4 = f & 63, tj = f >> 6;
        float4 acc = make_float4(0.f, 0.f, 0.f, 0.f);
#pragma unroll
        for (int ti = 0; ti < 16; ++ti) {
            g_blockcum[(ti * 8 + tj) * 64 + d4] = acc;
            float4 e[7];
#pragma unroll
            for (int s = 0; s < 7; ++s)
                e[s] = g_bot[((size_t)(ti * 8 + s) * 32 + 31) * D4 + d4];
#pragma unroll
            for (int s = 0; s < 7; ++s)
                if (s < tj) acc4(acc, e[s]);
        }
    }
}

// Corner SAT value: stored tile partial + the three cum tables.
__device__ __forceinline__ float4 cornerval(int n, int ct, int r, int c, int d4) {
    int ti = r >> 4, tj = c >> 5;
    float4 v = g_corner[(size_t)(n * 4 + ct) * D4 + d4];
    acc4(v, g_rowcum[((ti * 8 + tj) * 16 + (r & 15)) * 64 + d4]);
    acc4(v, g_colcum[((ti * 8 + tj) * 32 + (c & 31)) * 64 + d4]);
    acc4(v, g_blockcum[(ti * 8 + tj) * 64 + d4]);
    return v;
}

// ---------------------------------------------------------------------------
// Gather: 4 boxes per block, 64 float4 lanes per box; corner base loads are
// fully coalesced. Block 0 resets the tile counters for the next replay.
// ---------------------------------------------------------------------------
__global__ void __launch_bounds__(256) roi_gather(const float* __restrict__ boxes,
                                                  float4* __restrict__ out) {
    int n  = blockIdx.x * 4 + (threadIdx.x >> 6);
    int d4 = threadIdx.x & 63;

    int clo, chi, rlo, rhi;
    bounds4(boxes, n, clo, chi, rlo, rhi);
    int r2 = rhi - 1, c2 = chi - 1;
    int r1 = max(rlo - 1, 0), c1 = max(clo - 1, 0);

    float4 s = cornerval(n, 0, r2, c2, d4);
    if (rlo > 0) {
        float4 a = cornerval(n, 1, r1, c2, d4);
        s.x -= a.x; s.y -= a.y; s.z -= a.z; s.w -= a.w;
    }
    if (clo > 0) {
        float4 bb = cornerval(n, 2, r2, c1, d4);
        s.x -= bb.x; s.y -= bb.y; s.z -= bb.z; s.w -= bb.w;
        if (rlo > 0) acc4(s, cornerval(n, 3, r1, c1, d4));
    }

    float inv = 1.0f / (float)((rhi - rlo) * (chi - clo));
    s.x *= inv; s.y *= inv; s.z *= inv; s.w *= inv;
    out[(size_t)n * D4 + d4] = s;

    // Reset tile counters for the next replay (deterministic: runs after all
    // uses of g_tilecnt in this replay; next binning starts from zero).
    if (blockIdx.x == 0 && threadIdx.x < 128) g_tilecnt[threadIdx.x] = 0;
}

extern "C" void kernel_launch(void* const* d_in, const int* in_sizes, int n_in,
                              void* d_out, int out_size) {
    const float4* feat  = (const float4*)d_in[0];   // (256,256,256) fp32
    const float*  boxes = (const float*)d_in[1];    // (2048,4) fp32
    float4* out = (float4*)d_out;                   // (2048,256) fp32

    const int smem = (16 * RS + 16 * 4 * 4) * 4;    // 34816 B -> 6 blocks/SM
    cudaFuncSetAttribute(sat_tile, cudaFuncAttributeMaxDynamicSharedMemorySize, smem);

    binning<<<NB / 256, 256>>>(boxes);
    sat_tile<<<2048, 128, smem>>>(feat);
    fixups<<<130, 256>>>();                         // 33280 threads
    roi_gather<<<NB / 4, 256>>>(boxes, out);
}